// round 5
// baseline (speedup 1.0000x reference)
#include <cuda_runtime.h>
#include <cuda_bf16.h>
#include <math.h>
#include <stdint.h>

#define Bx 128
#define Lx 256
#define HIDx 768
#define HID2x 1536
#define CDIMx 192
#define SDIMx 128
#define NPROJx 128
#define FDIMx 321
#define BIGF 1000000000.0f

typedef unsigned long long u64;

// ---------------- scratch ----------------
__device__ float g_rep[Bx * HID2x];
__device__ float g_Pt[(size_t)Bx * NPROJx * Lx];    // [b][p][l]
__device__ float g_feat[Bx * FDIMx];                // only col 320 (d_ot) used
__device__ float g_partial[32 * Bx * 320];          // split-K partials (z=32)
__device__ int   g_mcnt[Bx];

#define FMA2(d, a, b) \
    asm("fma.rn.f32x2 %0, %1, %2, %0;" : "+l"(d) : "l"(a), "l"(b))

// ================= K1: masks, counts, cls, mean0-mean1 -> rep =================
__global__ void k1_stats(const float* __restrict__ H,
                         const int* __restrict__ tt,
                         const int* __restrict__ m) {
    int b = blockIdx.x;
    int c = blockIdx.y;
    int tid = threadIdx.x; // 256
    __shared__ float sf0[Lx], sf1[Lx];
    __shared__ float sc0, sc1;

    int t = tt[b * Lx + tid];
    int mm = m[b * Lx + tid];
    sf0[tid] = (t == 0 && mm == 1) ? 1.f : 0.f;
    sf1[tid] = (t == 1 && mm == 1) ? 1.f : 0.f;
    __syncthreads();

    if (tid == 0) {
        int c0 = 0, c1 = 0;
        for (int l = 0; l < Lx; l++) { c0 += (sf0[l] > 0.5f); c1 += (sf1[l] > 0.5f); }
        if (c == 0) {
            g_mcnt[b] = min(c0, c1);
            g_feat[b * FDIMx + 320] = 0.f;
        }
        sc0 = fmaxf((float)c0, 1.f);
        sc1 = fmaxf((float)c1, 1.f);
    }
    __syncthreads();

    int h = c * 256 + tid;
    const float* Hb = H + (size_t)b * Lx * HIDx;
    float s0 = 0.f, s1 = 0.f;
#pragma unroll 4
    for (int l = 0; l < Lx; l++) {
        float v = Hb[(size_t)l * HIDx + h];
        s0 += sf0[l] * v;
        s1 += sf1[l] * v;
    }
    g_rep[(size_t)b * HID2x + h]        = Hb[h];
    g_rep[(size_t)b * HID2x + HIDx + h] = s0 / sc0 - s1 / sc1;
}

// ============ K2 (FFMA2): Pt[b][p][l] = sum_h H[b,l,h]*proj[p,h] ============
// One CTA per b. Tile 256l x 128p, K-chunks of 16, double buffered.
// proj stored DUPLICATED in smem so the packed FMA2 b-operand is one LDS.64.
#define K2_HS_STRIDE 258
#define K2_HS_SZ (16 * K2_HS_STRIDE)        // floats per H buffer
#define K2_PD_SZ (16 * 256)                 // floats per dup-proj buffer
#define K2_BUFSZ (K2_HS_SZ + K2_PD_SZ)
#define K2_SMEM  (2 * K2_BUFSZ * 4)         // 65792 bytes

__global__ void __launch_bounds__(256, 1) k2_ffma2(const float* __restrict__ H,
                                                   const float* __restrict__ proj) {
    extern __shared__ float sm[];
    int b = blockIdx.x;
    int tid = threadIdx.x;
    int tx = tid & 15;           // p group: p = tx*8 + j
    int ty = tid >> 4;           // l group: l = ty*16 + ...

    const float* Hb = H + (size_t)b * Lx * HIDx;

    int pl = tid >> 1;           // proj row this thread stages (0..127)
    int ph = (tid & 1) * 8;      // k sub-offset (0 or 8)
    int txp = pl >> 3;
    int jp = pl & 7;
    int pd_base = jp * 32 + txp * 2;

    u64 acc[8][8];
#pragma unroll
    for (int i = 0; i < 8; i++)
#pragma unroll
        for (int j = 0; j < 8; j++) acc[i][j] = 0ull;

    float4 hreg[4], preg[2];
    // prefetch chunk 0
    {
        const float* hp = Hb + (size_t)tid * HIDx;
#pragma unroll
        for (int q = 0; q < 4; q++) hreg[q] = reinterpret_cast<const float4*>(hp)[q];
        const float* pp = proj + (size_t)pl * HIDx + ph;
        preg[0] = reinterpret_cast<const float4*>(pp)[0];
        preg[1] = reinterpret_cast<const float4*>(pp)[1];
    }

    for (int c = 0; c < 48; c++) {
        float* hsb = sm + (c & 1) * K2_BUFSZ;
        float* pdb = hsb + K2_HS_SZ;

        // ---- stage registers -> smem ----
        {
            float fh[16] = {hreg[0].x, hreg[0].y, hreg[0].z, hreg[0].w,
                            hreg[1].x, hreg[1].y, hreg[1].z, hreg[1].w,
                            hreg[2].x, hreg[2].y, hreg[2].z, hreg[2].w,
                            hreg[3].x, hreg[3].y, hreg[3].z, hreg[3].w};
#pragma unroll
            for (int k = 0; k < 16; k++) hsb[k * K2_HS_STRIDE + tid] = fh[k];

            float fp[8] = {preg[0].x, preg[0].y, preg[0].z, preg[0].w,
                           preg[1].x, preg[1].y, preg[1].z, preg[1].w};
#pragma unroll
            for (int e = 0; e < 8; e++) {
                float v = fp[e];
                *reinterpret_cast<float2*>(pdb + (ph + e) * 256 + pd_base) = make_float2(v, v);
            }
        }
        __syncthreads();

        // ---- prefetch next chunk ----
        if (c < 47) {
            int k0 = (c + 1) * 16;
            const float* hp = Hb + (size_t)tid * HIDx + k0;
#pragma unroll
            for (int q = 0; q < 4; q++) hreg[q] = reinterpret_cast<const float4*>(hp)[q];
            const float* pp = proj + (size_t)pl * HIDx + k0 + ph;
            preg[0] = reinterpret_cast<const float4*>(pp)[0];
            preg[1] = reinterpret_cast<const float4*>(pp)[1];
        }

        // ---- compute 16 k ----
#pragma unroll
        for (int k = 0; k < 16; k++) {
            const u64* hp2 = reinterpret_cast<const u64*>(hsb + k * K2_HS_STRIDE + ty * 16);
            u64 h0 = hp2[0], h1 = hp2[1], h2 = hp2[2], h3 = hp2[3];
            u64 h4 = hp2[4], h5 = hp2[5], h6 = hp2[6], h7 = hp2[7];
            const u64* pp2 = reinterpret_cast<const u64*>(pdb + k * 256 + tx * 2);
#pragma unroll
            for (int j = 0; j < 8; j++) {
                u64 pd = pp2[j * 16];
                FMA2(acc[0][j], h0, pd);
                FMA2(acc[1][j], h1, pd);
                FMA2(acc[2][j], h2, pd);
                FMA2(acc[3][j], h3, pd);
                FMA2(acc[4][j], h4, pd);
                FMA2(acc[5][j], h5, pd);
                FMA2(acc[6][j], h6, pd);
                FMA2(acc[7][j], h7, pd);
            }
        }
        __syncthreads();
    }

    // ---- epilogue: acc[(l pair i), (p j)] -> g_Pt[b][p][l] ----
    size_t base = (size_t)b * NPROJx * Lx;
#pragma unroll
    for (int j = 0; j < 8; j++) {
        int p = tx * 8 + j;
        u64* dst = reinterpret_cast<u64*>(g_Pt + base + (size_t)p * Lx + ty * 16);
#pragma unroll
        for (int i = 0; i < 8; i++) dst[i] = acc[i][j];
    }
}

// ================= K3: per-(b,p) bitonic sorts + mean |diff| =====
__device__ __forceinline__ void cex_asc(float& a, float& b) {
    float lo = fminf(a, b);
    float hi = fmaxf(a, b);
    a = lo; b = hi;
}

__device__ __forceinline__ void sort256(float v[8], int lane) {
    const unsigned FULL = 0xffffffffu;
    for (int k = 2; k <= 256; k <<= 1) {
        for (int j = k >> 1; j > 0; j >>= 1) {
            if (j >= 32) {
                int jr = j >> 5;
                int kr = k >> 5;
#pragma unroll
                for (int r = 0; r < 8; r++) {
                    if ((r & jr) == 0) {
                        if ((r & kr) == 0) cex_asc(v[r], v[r | jr]);
                        else               cex_asc(v[r | jr], v[r]);
                    }
                }
            } else {
#pragma unroll
                for (int r = 0; r < 8; r++) {
                    int idx = r * 32 + lane;
                    float other = __shfl_xor_sync(FULL, v[r], j);
                    bool lower = (idx & j) == 0;
                    bool asc   = (idx & k) == 0;
                    bool takeMin = (lower == asc);
                    v[r] = takeMin ? fminf(v[r], other) : fmaxf(v[r], other);
                }
            }
        }
    }
}

__global__ void k3_sort(const int* __restrict__ tt, const int* __restrict__ m) {
    int b = blockIdx.y;
    int tid = threadIdx.x;          // 256 threads = 8 warps
    int warp = tid >> 5, lane = tid & 31;
    __shared__ int tag[Lx];

    int t = tt[b * Lx + tid];
    int mm = m[b * Lx + tid];
    tag[tid] = (mm == 1) ? t : 2;
    __syncthreads();

    int p = blockIdx.x * 8 + warp;
    const float* col = g_Pt + ((size_t)b * NPROJx + p) * Lx;

    float a[8], c[8];
#pragma unroll
    for (int r = 0; r < 8; r++) {
        int l = r * 32 + lane;
        float v = col[l];
        int tg = tag[l];
        a[r] = (tg == 0) ? v : BIGF;
        c[r] = (tg == 1) ? v : BIGF;
    }
    sort256(a, lane);
    sort256(c, lane);

    int mc = g_mcnt[b];
    float s = 0.f;
#pragma unroll
    for (int r = 0; r < 8; r++) {
        int idx = r * 32 + lane;
        if (idx < mc) s += fabsf(a[r] - c[r]);
    }
#pragma unroll
    for (int o = 16; o > 0; o >>= 1) s += __shfl_down_sync(0xffffffffu, s, o);

    if (lane == 0) {
        float mean = s / (float)max(mc, 1);
        atomicMax(reinterpret_cast<int*>(&g_feat[b * FDIMx + 320]), __float_as_int(mean));
    }
}

// ===== K4a: feature GEMM (split-K z=32): partial[z][b][f] = sum_k rep*W =====
__global__ void __launch_bounds__(256) k4a_featgemm(const float* __restrict__ Wc,
                                                    const float* __restrict__ Ws) {
    __shared__ float repS[16][32];
    __shared__ float wS[16][64];

    int ftile = blockIdx.x * 64;   // 0..4
    int btile = blockIdx.y * 32;   // 0..3
    int kc    = blockIdx.z * 48;   // 0..31
    int tid = threadIdx.x;
    int tx = tid & 15;
    int ty = tid >> 4;

    float acc[2][4];
#pragma unroll
    for (int i = 0; i < 2; i++)
#pragma unroll
        for (int j = 0; j < 4; j++) acc[i][j] = 0.f;

    for (int k0 = 0; k0 < 48; k0 += 16) {
#pragma unroll
        for (int q = 0; q < 2; q++) {
            int e = tid + q * 256;
            int kk = e & 15, bb = e >> 4;
            repS[kk][bb] = g_rep[(size_t)(btile + bb) * HID2x + kc + k0 + kk];
        }
#pragma unroll
        for (int q = 0; q < 4; q++) {
            int e = tid + q * 256;
            int kk = e & 15, ff = e >> 4;
            int f = ftile + ff;
            const float* Wr = (f < CDIMx) ? (Wc + (size_t)f * HID2x)
                                          : (Ws + (size_t)(f - CDIMx) * HID2x);
            wS[kk][ff] = Wr[kc + k0 + kk];
        }
        __syncthreads();

#pragma unroll
        for (int kk = 0; kk < 16; kk++) {
            float4 wv = *reinterpret_cast<const float4*>(&wS[kk][tx * 4]);
            float r0 = repS[kk][ty * 2];
            float r1 = repS[kk][ty * 2 + 1];
            acc[0][0] += r0 * wv.x; acc[0][1] += r0 * wv.y;
            acc[0][2] += r0 * wv.z; acc[0][3] += r0 * wv.w;
            acc[1][0] += r1 * wv.x; acc[1][1] += r1 * wv.y;
            acc[1][2] += r1 * wv.z; acc[1][3] += r1 * wv.w;
        }
        __syncthreads();
    }

#pragma unroll
    for (int i = 0; i < 2; i++) {
        int bb = btile + ty * 2 + i;
        float4 o = make_float4(acc[i][0], acc[i][1], acc[i][2], acc[i][3]);
        *reinterpret_cast<float4*>(&g_partial[((size_t)blockIdx.z * Bx + bb) * 320 + ftile + tx * 4]) = o;
    }
}

// ===== K5: combine split-K + gate, LayerNorm(321), classifier =========
__device__ __forceinline__ float blockReduceSum(float val, float* sbuf) {
    int tid = threadIdx.x;
#pragma unroll
    for (int o = 16; o > 0; o >>= 1) val += __shfl_down_sync(0xffffffffu, val, o);
    if ((tid & 31) == 0) sbuf[tid >> 5] = val;
    __syncthreads();
    if (tid < 32) {
        int nw = (blockDim.x + 31) >> 5;
        float r = (tid < nw) ? sbuf[tid] : 0.f;
#pragma unroll
        for (int o = 16; o > 0; o >>= 1) r += __shfl_down_sync(0xffffffffu, r, o);
        if (tid == 0) sbuf[32] = r;
    }
    __syncthreads();
    float out = sbuf[32];
    __syncthreads();
    return out;
}

__global__ void k5_ln_cls(const float* __restrict__ bc,
                          const float* __restrict__ bs,
                          const float* __restrict__ gate,
                          const float* __restrict__ ln_g,
                          const float* __restrict__ ln_b,
                          const float* __restrict__ Wcls,
                          const float* __restrict__ bcls,
                          float* __restrict__ out) {
    __shared__ float sbuf[33];
    int b = blockIdx.x;
    int f = threadIdx.x; // 384 threads
    bool act = (f < FDIMx);

    float x = 0.f;
    if (f < 320) {
        float s = 0.f;
#pragma unroll
        for (int z = 0; z < 32; z++) s += g_partial[((size_t)z * Bx + b) * 320 + f];
        float g = 1.f / (1.f + expf(-gate[0]));
        if (f < CDIMx) x = (s + bc[f]) * (1.f - g);
        else           x = (s + bs[f - CDIMx]) * g;
    } else if (f == 320) {
        x = g_feat[b * FDIMx + 320];
    }

    float S  = blockReduceSum(x, sbuf);
    float SS = blockReduceSum(x * x, sbuf);
    float mean = S / (float)FDIMx;
    float var  = SS / (float)FDIMx - mean * mean;
    float inv  = rsqrtf(var + 1e-5f);

    float nrm = act ? ((x - mean) * inv * ln_g[f] + ln_b[f]) : 0.f;
    float w0 = act ? Wcls[f] : 0.f;
    float w1 = act ? Wcls[FDIMx + f] : 0.f;

    float s0 = blockReduceSum(nrm * w0, sbuf);
    float s1 = blockReduceSum(nrm * w1, sbuf);
    if (f == 0) {
        out[b * 2 + 0] = s0 + bcls[0];
        out[b * 2 + 1] = s1 + bcls[1];
    }
}

// =================================== launch ======================================
extern "C" void kernel_launch(void* const* d_in, const int* in_sizes, int n_in,
                              void* d_out, int out_size) {
    const float* H    = (const float*)d_in[0];
    const int*   tt   = (const int*)d_in[1];
    const int*   m    = (const int*)d_in[2];
    const float* Wc   = (const float*)d_in[3];
    const float* bc   = (const float*)d_in[4];
    const float* Ws   = (const float*)d_in[5];
    const float* bs   = (const float*)d_in[6];
    const float* gate = (const float*)d_in[7];
    const float* ln_g = (const float*)d_in[8];
    const float* ln_b = (const float*)d_in[9];
    const float* Wcls = (const float*)d_in[10];
    const float* bcls = (const float*)d_in[11];
    const float* proj = (const float*)d_in[12];
    float* out = (float*)d_out;

    cudaFuncSetAttribute(k2_ffma2, cudaFuncAttributeMaxDynamicSharedMemorySize, K2_SMEM);

    k1_stats<<<dim3(Bx, 3), 256>>>(H, tt, m);
    k2_ffma2<<<Bx, 256, K2_SMEM>>>(H, proj);
    k3_sort<<<dim3(16, Bx), 256>>>(tt, m);
    k4a_featgemm<<<dim3(5, 4, 32), 256>>>(Wc, Ws);
    k5_ln_cls<<<Bx, 384>>>(bc, bs, gate, ln_g, ln_b, Wcls, bcls, out);
}

// round 6
// speedup vs baseline: 1.3033x; 1.3033x over previous
#include <cuda_runtime.h>
#include <cuda_bf16.h>
#include <math.h>
#include <stdint.h>

#define Bx 128
#define Lx 256
#define HIDx 768
#define HID2x 1536
#define CDIMx 192
#define SDIMx 128
#define NPROJx 128
#define FDIMx 321
#define BIGF 1000000000.0f

// ---------------- scratch ----------------
__device__ float g_rep[Bx * HID2x];
__device__ float g_Pt[(size_t)Bx * NPROJx * Lx];    // [b][p][l]
__device__ float g_feat[Bx * FDIMx];                // only col 320 (d_ot) used
__device__ float g_partial[32 * Bx * 320];          // split-K partials (z=32)
__device__ int   g_mcnt[Bx];
__device__ __nv_bfloat16 g_Hhi[(size_t)Bx * Lx * HIDx];
__device__ __nv_bfloat16 g_Hlo[(size_t)Bx * Lx * HIDx];
__device__ __nv_bfloat16 g_phi[NPROJx * HIDx];
__device__ __nv_bfloat16 g_plo[NPROJx * HIDx];

// ---------------- helpers ----------------
__device__ __forceinline__ uint32_t smem_u32(const void* p) {
    uint32_t a;
    asm("{ .reg .u64 t; cvta.to.shared.u64 t, %1; cvt.u32.u64 %0, t; }" : "=r"(a) : "l"(p));
    return a;
}

// split float4 into bf16 hi / lo packed words (hi: 4 bf16 in uint2, lo likewise)
__device__ __forceinline__ void cvt4_hilo(float4 v, uint2& hi, uint2& lo) {
    uint32_t h0, h1, l0, l1;
    asm("cvt.rn.bf16x2.f32 %0, %1, %2;" : "=r"(h0) : "f"(v.y), "f"(v.x));
    asm("cvt.rn.bf16x2.f32 %0, %1, %2;" : "=r"(h1) : "f"(v.w), "f"(v.z));
    float hx = __uint_as_float(h0 << 16);
    float hy = __uint_as_float(h0 & 0xffff0000u);
    float hz = __uint_as_float(h1 << 16);
    float hw = __uint_as_float(h1 & 0xffff0000u);
    asm("cvt.rn.bf16x2.f32 %0, %1, %2;" : "=r"(l0) : "f"(v.y - hy), "f"(v.x - hx));
    asm("cvt.rn.bf16x2.f32 %0, %1, %2;" : "=r"(l1) : "f"(v.w - hw), "f"(v.z - hz));
    hi = make_uint2(h0, h1);
    lo = make_uint2(l0, l1);
}

#define LDSM4(R0, R1, R2, R3, ADDR) \
    asm volatile("ldmatrix.sync.aligned.m8n8.x4.shared.b16 {%0,%1,%2,%3}, [%4];" \
        : "=r"(R0), "=r"(R1), "=r"(R2), "=r"(R3) : "r"(ADDR))

#define MMA_BF16(D, A, B) \
    asm volatile("mma.sync.aligned.m16n8k16.row.col.f32.bf16.bf16.f32 " \
        "{%0,%1,%2,%3}, {%4,%5,%6,%7}, {%8,%9}, {%0,%1,%2,%3};" \
        : "+f"((D)[0]), "+f"((D)[1]), "+f"((D)[2]), "+f"((D)[3]) \
        : "r"((A)[0]), "r"((A)[1]), "r"((A)[2]), "r"((A)[3]), \
          "r"((B)[0]), "r"((B)[1]))

// ================= K0: convert fp32 -> bf16 hi/lo =================
__global__ void k0_cvt(const float* __restrict__ x, int which, int n4) {
    int i = blockIdx.x * blockDim.x + threadIdx.x;
    if (i >= n4) return;
    float4 v = reinterpret_cast<const float4*>(x)[i];
    uint2 h, l;
    cvt4_hilo(v, h, l);
    if (which == 0) {
        reinterpret_cast<uint2*>(g_Hhi)[i] = h;
        reinterpret_cast<uint2*>(g_Hlo)[i] = l;
    } else {
        reinterpret_cast<uint2*>(g_phi)[i] = h;
        reinterpret_cast<uint2*>(g_plo)[i] = l;
    }
}

// ================= K1: masks, counts, cls, mean0-mean1 -> rep =================
__global__ void k1_stats(const float* __restrict__ H,
                         const int* __restrict__ tt,
                         const int* __restrict__ m) {
    int b = blockIdx.x;
    int c = blockIdx.y;
    int tid = threadIdx.x; // 256
    __shared__ float sf0[Lx], sf1[Lx];
    __shared__ float sc0, sc1;

    int t = tt[b * Lx + tid];
    int mm = m[b * Lx + tid];
    sf0[tid] = (t == 0 && mm == 1) ? 1.f : 0.f;
    sf1[tid] = (t == 1 && mm == 1) ? 1.f : 0.f;
    __syncthreads();

    if (tid == 0) {
        int c0 = 0, c1 = 0;
        for (int l = 0; l < Lx; l++) { c0 += (sf0[l] > 0.5f); c1 += (sf1[l] > 0.5f); }
        if (c == 0) {
            g_mcnt[b] = min(c0, c1);
            g_feat[b * FDIMx + 320] = 0.f;
        }
        sc0 = fmaxf((float)c0, 1.f);
        sc1 = fmaxf((float)c1, 1.f);
    }
    __syncthreads();

    int h = c * 256 + tid;
    const float* Hb = H + (size_t)b * Lx * HIDx;
    float s0 = 0.f, s1 = 0.f;
#pragma unroll 4
    for (int l = 0; l < Lx; l++) {
        float v = Hb[(size_t)l * HIDx + h];
        s0 += sf0[l] * v;
        s1 += sf1[l] * v;
    }
    g_rep[(size_t)b * HID2x + h]        = Hb[h];
    g_rep[(size_t)b * HID2x + HIDx + h] = s0 / sc0 - s1 / sc1;
}

// ============ K2 (bf16 HMMA hi/lo): Pt[b][p][l] = sum_h H[b,l,h]*proj[p,h] ============
// CTA = (b, l-half): D[M=128 l][N=128 p], K=768 in 24 chunks of 32.
// smem per buffer: Ah | Al | Bh | Bl, each 128 rows x 32 bf16 (64B rows, swizzled), 8KB.
#define K2_SMEM 65536

__global__ void __launch_bounds__(256) k2_hmma() {
    extern __shared__ char sm[];
    uint32_t sb = smem_u32(sm);
    int b = blockIdx.x;
    int l0 = blockIdx.y * 128;
    int tid = threadIdx.x;
    int lane = tid & 31, w = tid >> 5;
    int wm = w >> 2;       // 0..1 : m64 tile
    int wn = w & 3;        // 0..3 : n32 tile

    // ---- staging setup: thread stages 32B (16 bf16) per matrix variant per chunk
    int srow = tid >> 1;          // 0..127
    int half = tid & 1;           // which 16-elem half of the 32-k chunk
    const uint4* gAh = reinterpret_cast<const uint4*>(g_Hhi + ((size_t)b * Lx + l0 + srow) * HIDx) + half * 2;
    const uint4* gAl = reinterpret_cast<const uint4*>(g_Hlo + ((size_t)b * Lx + l0 + srow) * HIDx) + half * 2;
    const uint4* gBh = reinterpret_cast<const uint4*>(g_phi + (size_t)srow * HIDx) + half * 2;
    const uint4* gBl = reinterpret_cast<const uint4*>(g_plo + (size_t)srow * HIDx) + half * 2;
    int sw_s = (srow >> 1) & 3;
    uint32_t o0 = (uint32_t)srow * 64 + (uint32_t)(((half * 2)     ^ sw_s) * 16);
    uint32_t o1 = (uint32_t)srow * 64 + (uint32_t)(((half * 2 + 1) ^ sw_s) * 16);

    // ---- fragment address precompute
    uint32_t rowA[4]; uint32_t swA[4];
#pragma unroll
    for (int i = 0; i < 4; i++) {
        int r = wm * 64 + i * 16 + (lane & 15);
        rowA[i] = (uint32_t)r * 64;
        swA[i] = (uint32_t)((r >> 1) & 3);
    }
    uint32_t ua = (uint32_t)(lane >> 4);        // 0/1
    uint32_t rowB[2]; uint32_t swB[2];
#pragma unroll
    for (int j2 = 0; j2 < 2; j2++) {
        int r = wn * 32 + j2 * 16 + (lane & 7) + ((lane >> 4) << 3);
        rowB[j2] = (uint32_t)r * 64;
        swB[j2] = (uint32_t)((r >> 1) & 3);
    }
    uint32_t ub = (uint32_t)((lane >> 3) & 1);  // 0/1

    float acc[4][4][4];
#pragma unroll
    for (int i = 0; i < 4; i++)
#pragma unroll
        for (int j = 0; j < 4; j++)
#pragma unroll
            for (int r = 0; r < 4; r++) acc[i][j][r] = 0.f;

    uint4 pf[8];
    // prefetch + stage chunk 0
    {
        pf[0] = gAh[0]; pf[1] = gAh[1];
        pf[2] = gAl[0]; pf[3] = gAl[1];
        pf[4] = gBh[0]; pf[5] = gBh[1];
        pf[6] = gBl[0]; pf[7] = gBl[1];
        char* sp = sm;
        *reinterpret_cast<uint4*>(sp + 0     + o0) = pf[0];
        *reinterpret_cast<uint4*>(sp + 0     + o1) = pf[1];
        *reinterpret_cast<uint4*>(sp + 8192  + o0) = pf[2];
        *reinterpret_cast<uint4*>(sp + 8192  + o1) = pf[3];
        *reinterpret_cast<uint4*>(sp + 16384 + o0) = pf[4];
        *reinterpret_cast<uint4*>(sp + 16384 + o1) = pf[5];
        *reinterpret_cast<uint4*>(sp + 24576 + o0) = pf[6];
        *reinterpret_cast<uint4*>(sp + 24576 + o1) = pf[7];
    }
    __syncthreads();

    for (int c = 0; c < 24; c++) {
        int buf = c & 1;
        if (c < 23) {
            int off = (c + 1) * 4;   // 4 uint4 per chunk along k
            pf[0] = gAh[off]; pf[1] = gAh[off + 1];
            pf[2] = gAl[off]; pf[3] = gAl[off + 1];
            pf[4] = gBh[off]; pf[5] = gBh[off + 1];
            pf[6] = gBl[off]; pf[7] = gBl[off + 1];
        }

        uint32_t bb = sb + (uint32_t)buf * 32768;
#pragma unroll
        for (int sel = 0; sel < 2; sel++) {
            uint32_t u2 = (uint32_t)(sel * 2);
            uint32_t bfh[4][2], bfl[4][2];
#pragma unroll
            for (int j2 = 0; j2 < 2; j2++) {
                uint32_t ah = bb + 16384 + rowB[j2] + (((u2 + ub) ^ swB[j2]) << 4);
                uint32_t r0, r1, r2, r3;
                LDSM4(r0, r1, r2, r3, ah);
                bfh[j2 * 2][0] = r0; bfh[j2 * 2][1] = r1;
                bfh[j2 * 2 + 1][0] = r2; bfh[j2 * 2 + 1][1] = r3;
                uint32_t al = bb + 24576 + rowB[j2] + (((u2 + ub) ^ swB[j2]) << 4);
                LDSM4(r0, r1, r2, r3, al);
                bfl[j2 * 2][0] = r0; bfl[j2 * 2][1] = r1;
                bfl[j2 * 2 + 1][0] = r2; bfl[j2 * 2 + 1][1] = r3;
            }
            uint32_t af[4][4];
#pragma unroll
            for (int i = 0; i < 4; i++) {
                uint32_t a = bb + rowA[i] + (((u2 + ua) ^ swA[i]) << 4);
                LDSM4(af[i][0], af[i][1], af[i][2], af[i][3], a);
            }
#pragma unroll
            for (int i = 0; i < 4; i++)
#pragma unroll
                for (int j = 0; j < 4; j++) {
                    MMA_BF16(acc[i][j], af[i], bfh[j]);
                    MMA_BF16(acc[i][j], af[i], bfl[j]);
                }
#pragma unroll
            for (int i = 0; i < 4; i++) {
                uint32_t a = bb + 8192 + rowA[i] + (((u2 + ua) ^ swA[i]) << 4);
                LDSM4(af[i][0], af[i][1], af[i][2], af[i][3], a);
            }
#pragma unroll
            for (int i = 0; i < 4; i++)
#pragma unroll
                for (int j = 0; j < 4; j++) {
                    MMA_BF16(acc[i][j], af[i], bfh[j]);
                }
        }

        if (c < 23) {
            char* sp = sm + (1 - buf) * 32768;
            *reinterpret_cast<uint4*>(sp + 0     + o0) = pf[0];
            *reinterpret_cast<uint4*>(sp + 0     + o1) = pf[1];
            *reinterpret_cast<uint4*>(sp + 8192  + o0) = pf[2];
            *reinterpret_cast<uint4*>(sp + 8192  + o1) = pf[3];
            *reinterpret_cast<uint4*>(sp + 16384 + o0) = pf[4];
            *reinterpret_cast<uint4*>(sp + 16384 + o1) = pf[5];
            *reinterpret_cast<uint4*>(sp + 24576 + o0) = pf[6];
            *reinterpret_cast<uint4*>(sp + 24576 + o1) = pf[7];
        }
        __syncthreads();
    }

    // ---- epilogue: acc -> g_Pt[b][p][l]
    float* gp = g_Pt + (size_t)b * NPROJx * Lx + l0;
#pragma unroll
    for (int i = 0; i < 4; i++) {
        int lrow = wm * 64 + i * 16 + (lane >> 2);
#pragma unroll
        for (int j = 0; j < 4; j++) {
            int p = wn * 32 + j * 8 + (lane & 3) * 2;
            gp[(size_t)p * Lx + lrow]           = acc[i][j][0];
            gp[(size_t)(p + 1) * Lx + lrow]     = acc[i][j][1];
            gp[(size_t)p * Lx + lrow + 8]       = acc[i][j][2];
            gp[(size_t)(p + 1) * Lx + lrow + 8] = acc[i][j][3];
        }
    }
}

// ================= K3: per-(b,p) bitonic sorts + mean |diff| =====
__device__ __forceinline__ void cex_asc(float& a, float& b) {
    float lo = fminf(a, b);
    float hi = fmaxf(a, b);
    a = lo; b = hi;
}

__device__ __forceinline__ void sort256(float v[8], int lane) {
    const unsigned FULL = 0xffffffffu;
    for (int k = 2; k <= 256; k <<= 1) {
        for (int j = k >> 1; j > 0; j >>= 1) {
            if (j >= 32) {
                int jr = j >> 5;
                int kr = k >> 5;
#pragma unroll
                for (int r = 0; r < 8; r++) {
                    if ((r & jr) == 0) {
                        if ((r & kr) == 0) cex_asc(v[r], v[r | jr]);
                        else               cex_asc(v[r | jr], v[r]);
                    }
                }
            } else {
#pragma unroll
                for (int r = 0; r < 8; r++) {
                    int idx = r * 32 + lane;
                    float other = __shfl_xor_sync(FULL, v[r], j);
                    bool lower = (idx & j) == 0;
                    bool asc   = (idx & k) == 0;
                    bool takeMin = (lower == asc);
                    v[r] = takeMin ? fminf(v[r], other) : fmaxf(v[r], other);
                }
            }
        }
    }
}

__global__ void k3_sort(const int* __restrict__ tt, const int* __restrict__ m) {
    int b = blockIdx.y;
    int tid = threadIdx.x;          // 256 threads = 8 warps
    int warp = tid >> 5, lane = tid & 31;
    __shared__ int tag[Lx];

    int t = tt[b * Lx + tid];
    int mm = m[b * Lx + tid];
    tag[tid] = (mm == 1) ? t : 2;
    __syncthreads();

    int p = blockIdx.x * 8 + warp;
    const float* col = g_Pt + ((size_t)b * NPROJx + p) * Lx;

    float a[8], c[8];
#pragma unroll
    for (int r = 0; r < 8; r++) {
        int l = r * 32 + lane;
        float v = col[l];
        int tg = tag[l];
        a[r] = (tg == 0) ? v : BIGF;
        c[r] = (tg == 1) ? v : BIGF;
    }
    sort256(a, lane);
    sort256(c, lane);

    int mc = g_mcnt[b];
    float s = 0.f;
#pragma unroll
    for (int r = 0; r < 8; r++) {
        int idx = r * 32 + lane;
        if (idx < mc) s += fabsf(a[r] - c[r]);
    }
#pragma unroll
    for (int o = 16; o > 0; o >>= 1) s += __shfl_down_sync(0xffffffffu, s, o);

    if (lane == 0) {
        float mean = s / (float)max(mc, 1);
        atomicMax(reinterpret_cast<int*>(&g_feat[b * FDIMx + 320]), __float_as_int(mean));
    }
}

// ===== K4a: feature GEMM (split-K z=32): partial[z][b][f] = sum_k rep*W =====
__global__ void __launch_bounds__(256) k4a_featgemm(const float* __restrict__ Wc,
                                                    const float* __restrict__ Ws) {
    __shared__ float repS[16][32];
    __shared__ float wS[16][64];

    int ftile = blockIdx.x * 64;   // 0..4
    int btile = blockIdx.y * 32;   // 0..3
    int kc    = blockIdx.z * 48;   // 0..31
    int tid = threadIdx.x;
    int tx = tid & 15;
    int ty = tid >> 4;

    float acc[2][4];
#pragma unroll
    for (int i = 0; i < 2; i++)
#pragma unroll
        for (int j = 0; j < 4; j++) acc[i][j] = 0.f;

    for (int k0 = 0; k0 < 48; k0 += 16) {
#pragma unroll
        for (int q = 0; q < 2; q++) {
            int e = tid + q * 256;
            int kk = e & 15, bb = e >> 4;
            repS[kk][bb] = g_rep[(size_t)(btile + bb) * HID2x + kc + k0 + kk];
        }
#pragma unroll
        for (int q = 0; q < 4; q++) {
            int e = tid + q * 256;
            int kk = e & 15, ff = e >> 4;
            int f = ftile + ff;
            const float* Wr = (f < CDIMx) ? (Wc + (size_t)f * HID2x)
                                          : (Ws + (size_t)(f - CDIMx) * HID2x);
            wS[kk][ff] = Wr[kc + k0 + kk];
        }
        __syncthreads();

#pragma unroll
        for (int kk = 0; kk < 16; kk++) {
            float4 wv = *reinterpret_cast<const float4*>(&wS[kk][tx * 4]);
            float r0 = repS[kk][ty * 2];
            float r1 = repS[kk][ty * 2 + 1];
            acc[0][0] += r0 * wv.x; acc[0][1] += r0 * wv.y;
            acc[0][2] += r0 * wv.z; acc[0][3] += r0 * wv.w;
            acc[1][0] += r1 * wv.x; acc[1][1] += r1 * wv.y;
            acc[1][2] += r1 * wv.z; acc[1][3] += r1 * wv.w;
        }
        __syncthreads();
    }

#pragma unroll
    for (int i = 0; i < 2; i++) {
        int bb = btile + ty * 2 + i;
        float4 o = make_float4(acc[i][0], acc[i][1], acc[i][2], acc[i][3]);
        *reinterpret_cast<float4*>(&g_partial[((size_t)blockIdx.z * Bx + bb) * 320 + ftile + tx * 4]) = o;
    }
}

// ===== K5: combine split-K + gate, LayerNorm(321), classifier =========
__device__ __forceinline__ float blockReduceSum(float val, float* sbuf) {
    int tid = threadIdx.x;
#pragma unroll
    for (int o = 16; o > 0; o >>= 1) val += __shfl_down_sync(0xffffffffu, val, o);
    if ((tid & 31) == 0) sbuf[tid >> 5] = val;
    __syncthreads();
    if (tid < 32) {
        int nw = (blockDim.x + 31) >> 5;
        float r = (tid < nw) ? sbuf[tid] : 0.f;
#pragma unroll
        for (int o = 16; o > 0; o >>= 1) r += __shfl_down_sync(0xffffffffu, r, o);
        if (tid == 0) sbuf[32] = r;
    }
    __syncthreads();
    float out = sbuf[32];
    __syncthreads();
    return out;
}

__global__ void k5_ln_cls(const float* __restrict__ bc,
                          const float* __restrict__ bs,
                          const float* __restrict__ gate,
                          const float* __restrict__ ln_g,
                          const float* __restrict__ ln_b,
                          const float* __restrict__ Wcls,
                          const float* __restrict__ bcls,
                          float* __restrict__ out) {
    __shared__ float sbuf[33];
    int b = blockIdx.x;
    int f = threadIdx.x; // 384 threads
    bool act = (f < FDIMx);

    float x = 0.f;
    if (f < 320) {
        float s = 0.f;
#pragma unroll
        for (int z = 0; z < 32; z++) s += g_partial[((size_t)z * Bx + b) * 320 + f];
        float g = 1.f / (1.f + expf(-gate[0]));
        if (f < CDIMx) x = (s + bc[f]) * (1.f - g);
        else           x = (s + bs[f - CDIMx]) * g;
    } else if (f == 320) {
        x = g_feat[b * FDIMx + 320];
    }

    float S  = blockReduceSum(x, sbuf);
    float SS = blockReduceSum(x * x, sbuf);
    float mean = S / (float)FDIMx;
    float var  = SS / (float)FDIMx - mean * mean;
    float inv  = rsqrtf(var + 1e-5f);

    float nrm = act ? ((x - mean) * inv * ln_g[f] + ln_b[f]) : 0.f;
    float w0 = act ? Wcls[f] : 0.f;
    float w1 = act ? Wcls[FDIMx + f] : 0.f;

    float s0 = blockReduceSum(nrm * w0, sbuf);
    float s1 = blockReduceSum(nrm * w1, sbuf);
    if (f == 0) {
        out[b * 2 + 0] = s0 + bcls[0];
        out[b * 2 + 1] = s1 + bcls[1];
    }
}

// =================================== launch ======================================
extern "C" void kernel_launch(void* const* d_in, const int* in_sizes, int n_in,
                              void* d_out, int out_size) {
    const float* H    = (const float*)d_in[0];
    const int*   tt   = (const int*)d_in[1];
    const int*   m    = (const int*)d_in[2];
    const float* Wc   = (const float*)d_in[3];
    const float* bc   = (const float*)d_in[4];
    const float* Ws   = (const float*)d_in[5];
    const float* bs   = (const float*)d_in[6];
    const float* gate = (const float*)d_in[7];
    const float* ln_g = (const float*)d_in[8];
    const float* ln_b = (const float*)d_in[9];
    const float* Wcls = (const float*)d_in[10];
    const float* bcls = (const float*)d_in[11];
    const float* proj = (const float*)d_in[12];
    float* out = (float*)d_out;

    cudaFuncSetAttribute(k2_hmma, cudaFuncAttributeMaxDynamicSharedMemorySize, K2_SMEM);

    // convert H and proj to bf16 hi/lo
    k0_cvt<<<6144, 1024>>>(H, 0, (Bx * Lx * HIDx) / 4);
    k0_cvt<<<24, 1024>>>(proj, 1, (NPROJx * HIDx) / 4);

    k1_stats<<<dim3(Bx, 3), 256>>>(H, tt, m);
    k2_hmma<<<dim3(Bx, 2), 256, K2_SMEM>>>();
    k3_sort<<<dim3(16, Bx), 256>>>(tt, m);
    k4a_featgemm<<<dim3(5, 4, 32), 256>>>(Wc, Ws);
    k5_ln_cls<<<Bx, 384>>>(bc, bs, gate, ln_g, ln_b, Wcls, bcls, out);
}

// round 7
// speedup vs baseline: 1.3768x; 1.0564x over previous
#include <cuda_runtime.h>
#include <cuda_bf16.h>
#include <math.h>
#include <stdint.h>

#define Bx 128
#define Lx 256
#define HIDx 768
#define HID2x 1536
#define CDIMx 192
#define SDIMx 128
#define NPROJx 128
#define FDIMx 321
#define BIGF 1000000000.0f

// ---------------- scratch ----------------
__device__ float g_rep[Bx * HID2x];
__device__ float g_Pt[(size_t)Bx * NPROJx * Lx];    // [b][p][l]
__device__ float g_feat[Bx * FDIMx];                // only col 320 (d_ot) used
__device__ float g_partial[32 * Bx * 320];          // split-K partials (z=32)
__device__ int   g_mcnt[Bx];
__device__ __nv_bfloat16 g_phi[NPROJx * HIDx];
__device__ __nv_bfloat16 g_plo[NPROJx * HIDx];

// ---------------- helpers ----------------
__device__ __forceinline__ uint32_t smem_u32(const void* p) {
    uint32_t a;
    asm("{ .reg .u64 t; cvta.to.shared.u64 t, %1; cvt.u32.u64 %0, t; }" : "=r"(a) : "l"(p));
    return a;
}

// split float4 into bf16 hi / lo packed words (hi: 4 bf16 in uint2, lo likewise)
__device__ __forceinline__ void cvt4_hilo(float4 v, uint2& hi, uint2& lo) {
    uint32_t h0, h1, l0, l1;
    asm("cvt.rn.bf16x2.f32 %0, %1, %2;" : "=r"(h0) : "f"(v.y), "f"(v.x));
    asm("cvt.rn.bf16x2.f32 %0, %1, %2;" : "=r"(h1) : "f"(v.w), "f"(v.z));
    float hx = __uint_as_float(h0 << 16);
    float hy = __uint_as_float(h0 & 0xffff0000u);
    float hz = __uint_as_float(h1 << 16);
    float hw = __uint_as_float(h1 & 0xffff0000u);
    asm("cvt.rn.bf16x2.f32 %0, %1, %2;" : "=r"(l0) : "f"(v.y - hy), "f"(v.x - hx));
    asm("cvt.rn.bf16x2.f32 %0, %1, %2;" : "=r"(l1) : "f"(v.w - hw), "f"(v.z - hz));
    hi = make_uint2(h0, h1);
    lo = make_uint2(l0, l1);
}

#define LDSM4(R0, R1, R2, R3, ADDR) \
    asm volatile("ldmatrix.sync.aligned.m8n8.x4.shared.b16 {%0,%1,%2,%3}, [%4];" \
        : "=r"(R0), "=r"(R1), "=r"(R2), "=r"(R3) : "r"(ADDR))

#define MMA_BF16(D, A, B) \
    asm volatile("mma.sync.aligned.m16n8k16.row.col.f32.bf16.bf16.f32 " \
        "{%0,%1,%2,%3}, {%4,%5,%6,%7}, {%8,%9}, {%0,%1,%2,%3};" \
        : "+f"((D)[0]), "+f"((D)[1]), "+f"((D)[2]), "+f"((D)[3]) \
        : "r"((A)[0]), "r"((A)[1]), "r"((A)[2]), "r"((A)[3]), \
          "r"((B)[0]), "r"((B)[1]))

// ================= K0p: convert proj fp32 -> bf16 hi/lo (tiny) =================
__global__ void k0_cvt_proj(const float* __restrict__ x, int n4) {
    int i = blockIdx.x * blockDim.x + threadIdx.x;
    if (i >= n4) return;
    float4 v = reinterpret_cast<const float4*>(x)[i];
    uint2 h, l;
    cvt4_hilo(v, h, l);
    reinterpret_cast<uint2*>(g_phi)[i] = h;
    reinterpret_cast<uint2*>(g_plo)[i] = l;
}

// ================= K1: masks, counts, cls, mean0-mean1 -> rep =================
__global__ void k1_stats(const float* __restrict__ H,
                         const int* __restrict__ tt,
                         const int* __restrict__ m) {
    int b = blockIdx.x;
    int c = blockIdx.y;
    int tid = threadIdx.x; // 256
    __shared__ float sf0[Lx], sf1[Lx];
    __shared__ float sc0, sc1;

    int t = tt[b * Lx + tid];
    int mm = m[b * Lx + tid];
    sf0[tid] = (t == 0 && mm == 1) ? 1.f : 0.f;
    sf1[tid] = (t == 1 && mm == 1) ? 1.f : 0.f;
    __syncthreads();

    if (tid == 0) {
        int c0 = 0, c1 = 0;
        for (int l = 0; l < Lx; l++) { c0 += (sf0[l] > 0.5f); c1 += (sf1[l] > 0.5f); }
        if (c == 0) {
            g_mcnt[b] = min(c0, c1);
            g_feat[b * FDIMx + 320] = 0.f;
        }
        sc0 = fmaxf((float)c0, 1.f);
        sc1 = fmaxf((float)c1, 1.f);
    }
    __syncthreads();

    int h = c * 256 + tid;
    const float* Hb = H + (size_t)b * Lx * HIDx;
    float s0 = 0.f, s1 = 0.f;
#pragma unroll 8
    for (int l = 0; l < Lx; l++) {
        float v = Hb[(size_t)l * HIDx + h];
        s0 += sf0[l] * v;
        s1 += sf1[l] * v;
    }
    g_rep[(size_t)b * HID2x + h]        = Hb[h];
    g_rep[(size_t)b * HID2x + HIDx + h] = s0 / sc0 - s1 / sc1;
}

// ============ K2 (bf16 HMMA hi/lo, fused fp32->bf16 conversion) ============
// CTA = (b, l-half): D[M=128 l][N=128 p], K=768 in 24 chunks of 32.
// smem per buffer: Ah | Al | Bh | Bl, each 128 rows x 32 bf16 (64B rows, swizzled), 8KB.
#define K2_SMEM 65536

__global__ void __launch_bounds__(256) k2_hmma(const float* __restrict__ H) {
    extern __shared__ char sm[];
    uint32_t sb = smem_u32(sm);
    int b = blockIdx.x;
    int l0 = blockIdx.y * 128;
    int tid = threadIdx.x;
    int lane = tid & 31, w = tid >> 5;
    int wm = w >> 2;       // 0..1 : m64 tile
    int wn = w & 3;        // 0..3 : n32 tile

    // ---- staging setup: each thread covers 16 k-cols of one row per chunk
    int srow = tid >> 1;          // 0..127
    int half = tid & 1;           // which 16-elem half of the 32-k chunk
    // A from fp32 H: 4 float4 per chunk, consecutive from k = half*16
    const float4* gA = reinterpret_cast<const float4*>(H + ((size_t)(b * Lx) + l0 + srow) * HIDx) + half * 4;
    // B from pre-converted bf16 proj
    const uint4* gBh = reinterpret_cast<const uint4*>(g_phi + (size_t)srow * HIDx) + half * 2;
    const uint4* gBl = reinterpret_cast<const uint4*>(g_plo + (size_t)srow * HIDx) + half * 2;
    int sw_s = (srow >> 1) & 3;
    // B store offsets (two 16B blocks)
    uint32_t o0 = (uint32_t)srow * 64 + (uint32_t)(((half * 2)     ^ sw_s) * 16);
    uint32_t o1 = (uint32_t)srow * 64 + (uint32_t)(((half * 2 + 1) ^ sw_s) * 16);
    // A store offsets (four 8B pieces at 16B-block granularity)
    uint32_t oa[4];
#pragma unroll
    for (int q = 0; q < 4; q++) {
        uint32_t u = (uint32_t)(half * 2 + (q >> 1));
        oa[q] = (uint32_t)srow * 64 + ((u ^ (uint32_t)sw_s) << 4) + (uint32_t)((q & 1) * 8);
    }

    // ---- fragment address precompute
    uint32_t rowA[4]; uint32_t swA[4];
#pragma unroll
    for (int i = 0; i < 4; i++) {
        int r = wm * 64 + i * 16 + (lane & 15);
        rowA[i] = (uint32_t)r * 64;
        swA[i] = (uint32_t)((r >> 1) & 3);
    }
    uint32_t ua = (uint32_t)(lane >> 4);        // 0/1
    uint32_t rowB[2]; uint32_t swB[2];
#pragma unroll
    for (int j2 = 0; j2 < 2; j2++) {
        int r = wn * 32 + j2 * 16 + (lane & 7) + ((lane >> 4) << 3);
        rowB[j2] = (uint32_t)r * 64;
        swB[j2] = (uint32_t)((r >> 1) & 3);
    }
    uint32_t ub = (uint32_t)((lane >> 3) & 1);  // 0/1

    float acc[4][4][4];
#pragma unroll
    for (int i = 0; i < 4; i++)
#pragma unroll
        for (int j = 0; j < 4; j++)
#pragma unroll
            for (int r = 0; r < 4; r++) acc[i][j][r] = 0.f;

    float4 pfA[4];
    uint4 pfBh[2], pfBl[2];
    // prefetch + stage chunk 0
    {
#pragma unroll
        for (int q = 0; q < 4; q++) pfA[q] = gA[q];
        pfBh[0] = gBh[0]; pfBh[1] = gBh[1];
        pfBl[0] = gBl[0]; pfBl[1] = gBl[1];
        char* sp = sm;
#pragma unroll
        for (int q = 0; q < 4; q++) {
            uint2 hi, lo;
            cvt4_hilo(pfA[q], hi, lo);
            *reinterpret_cast<uint2*>(sp + 0    + oa[q]) = hi;
            *reinterpret_cast<uint2*>(sp + 8192 + oa[q]) = lo;
        }
        *reinterpret_cast<uint4*>(sp + 16384 + o0) = pfBh[0];
        *reinterpret_cast<uint4*>(sp + 16384 + o1) = pfBh[1];
        *reinterpret_cast<uint4*>(sp + 24576 + o0) = pfBl[0];
        *reinterpret_cast<uint4*>(sp + 24576 + o1) = pfBl[1];
    }
    __syncthreads();

    for (int c = 0; c < 24; c++) {
        int buf = c & 1;
        if (c < 23) {
            int offA = (c + 1) * 8;   // 8 float4 per row per chunk (32 fp32)
            int offB = (c + 1) * 4;   // 4 uint4 per row per chunk (32 bf16 x2B... per row 64B)
#pragma unroll
            for (int q = 0; q < 4; q++) pfA[q] = gA[offA + q];
            pfBh[0] = gBh[offB]; pfBh[1] = gBh[offB + 1];
            pfBl[0] = gBl[offB]; pfBl[1] = gBl[offB + 1];
        }

        uint32_t bb = sb + (uint32_t)buf * 32768;
#pragma unroll
        for (int sel = 0; sel < 2; sel++) {
            uint32_t u2 = (uint32_t)(sel * 2);
            uint32_t bfh[4][2], bfl[4][2];
#pragma unroll
            for (int j2 = 0; j2 < 2; j2++) {
                uint32_t ah = bb + 16384 + rowB[j2] + (((u2 + ub) ^ swB[j2]) << 4);
                uint32_t r0, r1, r2, r3;
                LDSM4(r0, r1, r2, r3, ah);
                bfh[j2 * 2][0] = r0; bfh[j2 * 2][1] = r1;
                bfh[j2 * 2 + 1][0] = r2; bfh[j2 * 2 + 1][1] = r3;
                uint32_t al = bb + 24576 + rowB[j2] + (((u2 + ub) ^ swB[j2]) << 4);
                LDSM4(r0, r1, r2, r3, al);
                bfl[j2 * 2][0] = r0; bfl[j2 * 2][1] = r1;
                bfl[j2 * 2 + 1][0] = r2; bfl[j2 * 2 + 1][1] = r3;
            }
            uint32_t af[4][4];
#pragma unroll
            for (int i = 0; i < 4; i++) {
                uint32_t a = bb + rowA[i] + (((u2 + ua) ^ swA[i]) << 4);
                LDSM4(af[i][0], af[i][1], af[i][2], af[i][3], a);
            }
#pragma unroll
            for (int i = 0; i < 4; i++)
#pragma unroll
                for (int j = 0; j < 4; j++) {
                    MMA_BF16(acc[i][j], af[i], bfh[j]);
                    MMA_BF16(acc[i][j], af[i], bfl[j]);
                }
#pragma unroll
            for (int i = 0; i < 4; i++) {
                uint32_t a = bb + 8192 + rowA[i] + (((u2 + ua) ^ swA[i]) << 4);
                LDSM4(af[i][0], af[i][1], af[i][2], af[i][3], a);
            }
#pragma unroll
            for (int i = 0; i < 4; i++)
#pragma unroll
                for (int j = 0; j < 4; j++) {
                    MMA_BF16(acc[i][j], af[i], bfh[j]);
                }
        }

        if (c < 23) {
            char* sp = sm + (1 - buf) * 32768;
#pragma unroll
            for (int q = 0; q < 4; q++) {
                uint2 hi, lo;
                cvt4_hilo(pfA[q], hi, lo);
                *reinterpret_cast<uint2*>(sp + 0    + oa[q]) = hi;
                *reinterpret_cast<uint2*>(sp + 8192 + oa[q]) = lo;
            }
            *reinterpret_cast<uint4*>(sp + 16384 + o0) = pfBh[0];
            *reinterpret_cast<uint4*>(sp + 16384 + o1) = pfBh[1];
            *reinterpret_cast<uint4*>(sp + 24576 + o0) = pfBl[0];
            *reinterpret_cast<uint4*>(sp + 24576 + o1) = pfBl[1];
        }
        __syncthreads();
    }

    // ---- epilogue: acc -> g_Pt[b][p][l]
    float* gp = g_Pt + (size_t)b * NPROJx * Lx + l0;
#pragma unroll
    for (int i = 0; i < 4; i++) {
        int lrow = wm * 64 + i * 16 + (lane >> 2);
#pragma unroll
        for (int j = 0; j < 4; j++) {
            int p = wn * 32 + j * 8 + (lane & 3) * 2;
            gp[(size_t)p * Lx + lrow]           = acc[i][j][0];
            gp[(size_t)(p + 1) * Lx + lrow]     = acc[i][j][1];
            gp[(size_t)p * Lx + lrow + 8]       = acc[i][j][2];
            gp[(size_t)(p + 1) * Lx + lrow + 8] = acc[i][j][3];
        }
    }
}

// ================= K3: per-(b,p) bitonic sorts + mean |diff| =====
__device__ __forceinline__ void cex_asc(float& a, float& b) {
    float lo = fminf(a, b);
    float hi = fmaxf(a, b);
    a = lo; b = hi;
}

__device__ __forceinline__ void sort256(float v[8], int lane) {
    const unsigned FULL = 0xffffffffu;
    for (int k = 2; k <= 256; k <<= 1) {
        for (int j = k >> 1; j > 0; j >>= 1) {
            if (j >= 32) {
                int jr = j >> 5;
                int kr = k >> 5;
#pragma unroll
                for (int r = 0; r < 8; r++) {
                    if ((r & jr) == 0) {
                        if ((r & kr) == 0) cex_asc(v[r], v[r | jr]);
                        else               cex_asc(v[r | jr], v[r]);
                    }
                }
            } else {
#pragma unroll
                for (int r = 0; r < 8; r++) {
                    int idx = r * 32 + lane;
                    float other = __shfl_xor_sync(FULL, v[r], j);
                    bool lower = (idx & j) == 0;
                    bool asc   = (idx & k) == 0;
                    bool takeMin = (lower == asc);
                    v[r] = takeMin ? fminf(v[r], other) : fmaxf(v[r], other);
                }
            }
        }
    }
}

__global__ void k3_sort(const int* __restrict__ tt, const int* __restrict__ m) {
    int b = blockIdx.y;
    int tid = threadIdx.x;          // 256 threads = 8 warps
    int warp = tid >> 5, lane = tid & 31;
    __shared__ int tag[Lx];

    int t = tt[b * Lx + tid];
    int mm = m[b * Lx + tid];
    tag[tid] = (mm == 1) ? t : 2;
    __syncthreads();

    int p = blockIdx.x * 8 + warp;
    const float* col = g_Pt + ((size_t)b * NPROJx + p) * Lx;

    float a[8], c[8];
#pragma unroll
    for (int r = 0; r < 8; r++) {
        int l = r * 32 + lane;
        float v = col[l];
        int tg = tag[l];
        a[r] = (tg == 0) ? v : BIGF;
        c[r] = (tg == 1) ? v : BIGF;
    }
    sort256(a, lane);
    sort256(c, lane);

    int mc = g_mcnt[b];
    float s = 0.f;
#pragma unroll
    for (int r = 0; r < 8; r++) {
        int idx = r * 32 + lane;
        if (idx < mc) s += fabsf(a[r] - c[r]);
    }
#pragma unroll
    for (int o = 16; o > 0; o >>= 1) s += __shfl_down_sync(0xffffffffu, s, o);

    if (lane == 0) {
        float mean = s / (float)max(mc, 1);
        atomicMax(reinterpret_cast<int*>(&g_feat[b * FDIMx + 320]), __float_as_int(mean));
    }
}

// ===== K4a: feature GEMM (split-K z=32): partial[z][b][f] = sum_k rep*W =====
__global__ void __launch_bounds__(256) k4a_featgemm(const float* __restrict__ Wc,
                                                    const float* __restrict__ Ws) {
    __shared__ float repS[16][32];
    __shared__ float wS[16][64];

    int ftile = blockIdx.x * 64;   // 0..4
    int btile = blockIdx.y * 32;   // 0..3
    int kc    = blockIdx.z * 48;   // 0..31
    int tid = threadIdx.x;
    int tx = tid & 15;
    int ty = tid >> 4;

    float acc[2][4];
#pragma unroll
    for (int i = 0; i < 2; i++)
#pragma unroll
        for (int j = 0; j < 4; j++) acc[i][j] = 0.f;

    for (int k0 = 0; k0 < 48; k0 += 16) {
#pragma unroll
        for (int q = 0; q < 2; q++) {
            int e = tid + q * 256;
            int kk = e & 15, bb = e >> 4;
            repS[kk][bb] = g_rep[(size_t)(btile + bb) * HID2x + kc + k0 + kk];
        }
#pragma unroll
        for (int q = 0; q < 4; q++) {
            int e = tid + q * 256;
            int kk = e & 15, ff = e >> 4;
            int f = ftile + ff;
            const float* Wr = (f < CDIMx) ? (Wc + (size_t)f * HID2x)
                                          : (Ws + (size_t)(f - CDIMx) * HID2x);
            wS[kk][ff] = Wr[kc + k0 + kk];
        }
        __syncthreads();

#pragma unroll
        for (int kk = 0; kk < 16; kk++) {
            float4 wv = *reinterpret_cast<const float4*>(&wS[kk][tx * 4]);
            float r0 = repS[kk][ty * 2];
            float r1 = repS[kk][ty * 2 + 1];
            acc[0][0] += r0 * wv.x; acc[0][1] += r0 * wv.y;
            acc[0][2] += r0 * wv.z; acc[0][3] += r0 * wv.w;
            acc[1][0] += r1 * wv.x; acc[1][1] += r1 * wv.y;
            acc[1][2] += r1 * wv.z; acc[1][3] += r1 * wv.w;
        }
        __syncthreads();
    }

#pragma unroll
    for (int i = 0; i < 2; i++) {
        int bb = btile + ty * 2 + i;
        float4 o = make_float4(acc[i][0], acc[i][1], acc[i][2], acc[i][3]);
        *reinterpret_cast<float4*>(&g_partial[((size_t)blockIdx.z * Bx + bb) * 320 + ftile + tx * 4]) = o;
    }
}

// ===== K5: combine split-K + gate, LayerNorm(321), classifier =========
__device__ __forceinline__ float blockReduceSum(float val, float* sbuf) {
    int tid = threadIdx.x;
#pragma unroll
    for (int o = 16; o > 0; o >>= 1) val += __shfl_down_sync(0xffffffffu, val, o);
    if ((tid & 31) == 0) sbuf[tid >> 5] = val;
    __syncthreads();
    if (tid < 32) {
        int nw = (blockDim.x + 31) >> 5;
        float r = (tid < nw) ? sbuf[tid] : 0.f;
#pragma unroll
        for (int o = 16; o > 0; o >>= 1) r += __shfl_down_sync(0xffffffffu, r, o);
        if (tid == 0) sbuf[32] = r;
    }
    __syncthreads();
    float out = sbuf[32];
    __syncthreads();
    return out;
}

__global__ void k5_ln_cls(const float* __restrict__ bc,
                          const float* __restrict__ bs,
                          const float* __restrict__ gate,
                          const float* __restrict__ ln_g,
                          const float* __restrict__ ln_b,
                          const float* __restrict__ Wcls,
                          const float* __restrict__ bcls,
                          float* __restrict__ out) {
    __shared__ float sbuf[33];
    int b = blockIdx.x;
    int f = threadIdx.x; // 384 threads
    bool act = (f < FDIMx);

    float x = 0.f;
    if (f < 320) {
        float s = 0.f;
#pragma unroll
        for (int z = 0; z < 32; z++) s += g_partial[((size_t)z * Bx + b) * 320 + f];
        float g = 1.f / (1.f + expf(-gate[0]));
        if (f < CDIMx) x = (s + bc[f]) * (1.f - g);
        else           x = (s + bs[f - CDIMx]) * g;
    } else if (f == 320) {
        x = g_feat[b * FDIMx + 320];
    }

    float S  = blockReduceSum(x, sbuf);
    float SS = blockReduceSum(x * x, sbuf);
    float mean = S / (float)FDIMx;
    float var  = SS / (float)FDIMx - mean * mean;
    float inv  = rsqrtf(var + 1e-5f);

    float nrm = act ? ((x - mean) * inv * ln_g[f] + ln_b[f]) : 0.f;
    float w0 = act ? Wcls[f] : 0.f;
    float w1 = act ? Wcls[FDIMx + f] : 0.f;

    float s0 = blockReduceSum(nrm * w0, sbuf);
    float s1 = blockReduceSum(nrm * w1, sbuf);
    if (f == 0) {
        out[b * 2 + 0] = s0 + bcls[0];
        out[b * 2 + 1] = s1 + bcls[1];
    }
}

// =================================== launch ======================================
extern "C" void kernel_launch(void* const* d_in, const int* in_sizes, int n_in,
                              void* d_out, int out_size) {
    const float* H    = (const float*)d_in[0];
    const int*   tt   = (const int*)d_in[1];
    const int*   m    = (const int*)d_in[2];
    const float* Wc   = (const float*)d_in[3];
    const float* bc   = (const float*)d_in[4];
    const float* Ws   = (const float*)d_in[5];
    const float* bs   = (const float*)d_in[6];
    const float* gate = (const float*)d_in[7];
    const float* ln_g = (const float*)d_in[8];
    const float* ln_b = (const float*)d_in[9];
    const float* Wcls = (const float*)d_in[10];
    const float* bcls = (const float*)d_in[11];
    const float* proj = (const float*)d_in[12];
    float* out = (float*)d_out;

    cudaFuncSetAttribute(k2_hmma, cudaFuncAttributeMaxDynamicSharedMemorySize, K2_SMEM);

    k0_cvt_proj<<<96, 256>>>(proj, (NPROJx * HIDx) / 4);
    k1_stats<<<dim3(Bx, 3), 256>>>(H, tt, m);
    k2_hmma<<<dim3(Bx, 2), 256, K2_SMEM>>>(H);
    k3_sort<<<dim3(16, Bx), 256>>>(tt, m);
    k4a_featgemm<<<dim3(5, 4, 32), 256>>>(Wc, Ws);
    k5_ln_cls<<<Bx, 384>>>(bc, bs, gate, ln_g, ln_b, Wcls, bcls, out);
}

// round 8
// speedup vs baseline: 2.1367x; 1.5519x over previous
#include <cuda_runtime.h>
#include <cuda_bf16.h>
#include <math.h>
#include <stdint.h>

#define Bx 128
#define Lx 256
#define HIDx 768
#define HID2x 1536
#define CDIMx 192
#define SDIMx 128
#define NPROJx 128
#define FDIMx 321
#define BIGF 1000000000.0f

// ---------------- scratch ----------------
__device__ float g_rep[Bx * HID2x];
__device__ float g_Pt[(size_t)Bx * NPROJx * Lx];    // [b][p][l]
__device__ float g_feat[Bx * FDIMx];                // only col 320 (d_ot) used
__device__ float g_partial[32 * Bx * 320];          // split-K partials (z=32)
__device__ int   g_mcnt[Bx];
__device__ __nv_bfloat16 g_phi[NPROJx * HIDx];
__device__ __nv_bfloat16 g_plo[NPROJx * HIDx];

// ---------------- helpers ----------------
__device__ __forceinline__ uint32_t smem_u32(const void* p) {
    uint32_t a;
    asm("{ .reg .u64 t; cvta.to.shared.u64 t, %1; cvt.u32.u64 %0, t; }" : "=r"(a) : "l"(p));
    return a;
}

// split float4 into bf16 hi / lo packed words (hi: 4 bf16 in uint2, lo likewise)
__device__ __forceinline__ void cvt4_hilo(float4 v, uint2& hi, uint2& lo) {
    uint32_t h0, h1, l0, l1;
    asm("cvt.rn.bf16x2.f32 %0, %1, %2;" : "=r"(h0) : "f"(v.y), "f"(v.x));
    asm("cvt.rn.bf16x2.f32 %0, %1, %2;" : "=r"(h1) : "f"(v.w), "f"(v.z));
    float hx = __uint_as_float(h0 << 16);
    float hy = __uint_as_float(h0 & 0xffff0000u);
    float hz = __uint_as_float(h1 << 16);
    float hw = __uint_as_float(h1 & 0xffff0000u);
    asm("cvt.rn.bf16x2.f32 %0, %1, %2;" : "=r"(l0) : "f"(v.y - hy), "f"(v.x - hx));
    asm("cvt.rn.bf16x2.f32 %0, %1, %2;" : "=r"(l1) : "f"(v.w - hw), "f"(v.z - hz));
    hi = make_uint2(h0, h1);
    lo = make_uint2(l0, l1);
}

#define LDSM4(R0, R1, R2, R3, ADDR) \
    asm volatile("ldmatrix.sync.aligned.m8n8.x4.shared.b16 {%0,%1,%2,%3}, [%4];" \
        : "=r"(R0), "=r"(R1), "=r"(R2), "=r"(R3) : "r"(ADDR))

#define MMA_BF16(D, A, B) \
    asm volatile("mma.sync.aligned.m16n8k16.row.col.f32.bf16.bf16.f32 " \
        "{%0,%1,%2,%3}, {%4,%5,%6,%7}, {%8,%9}, {%0,%1,%2,%3};" \
        : "+f"((D)[0]), "+f"((D)[1]), "+f"((D)[2]), "+f"((D)[3]) \
        : "r"((A)[0]), "r"((A)[1]), "r"((A)[2]), "r"((A)[3]), \
          "r"((B)[0]), "r"((B)[1]))

// ================= K0p: convert proj fp32 -> bf16 hi/lo (tiny) =================
__global__ void k0_cvt_proj(const float* __restrict__ x, int n4) {
    int i = blockIdx.x * blockDim.x + threadIdx.x;
    if (i >= n4) return;
    float4 v = reinterpret_cast<const float4*>(x)[i];
    uint2 h, l;
    cvt4_hilo(v, h, l);
    reinterpret_cast<uint2*>(g_phi)[i] = h;
    reinterpret_cast<uint2*>(g_plo)[i] = l;
}

// ================= K1: masks, counts, cls, mean0-mean1 -> rep =================
__global__ void k1_stats(const float* __restrict__ H,
                         const int* __restrict__ tt,
                         const int* __restrict__ m) {
    int b = blockIdx.x;
    int c = blockIdx.y;
    int tid = threadIdx.x; // 256
    __shared__ float sf0[Lx], sf1[Lx];
    __shared__ float sc0, sc1;

    int t = tt[b * Lx + tid];
    int mm = m[b * Lx + tid];
    sf0[tid] = (t == 0 && mm == 1) ? 1.f : 0.f;
    sf1[tid] = (t == 1 && mm == 1) ? 1.f : 0.f;
    __syncthreads();

    if (tid == 0) {
        int c0 = 0, c1 = 0;
        for (int l = 0; l < Lx; l++) { c0 += (sf0[l] > 0.5f); c1 += (sf1[l] > 0.5f); }
        if (c == 0) {
            g_mcnt[b] = min(c0, c1);
            g_feat[b * FDIMx + 320] = 0.f;
        }
        sc0 = fmaxf((float)c0, 1.f);
        sc1 = fmaxf((float)c1, 1.f);
    }
    __syncthreads();

    int h = c * 256 + tid;
    const float* Hb = H + (size_t)b * Lx * HIDx;
    float s0 = 0.f, s1 = 0.f;
#pragma unroll 8
    for (int l = 0; l < Lx; l++) {
        float v = Hb[(size_t)l * HIDx + h];
        s0 += sf0[l] * v;
        s1 += sf1[l] * v;
    }
    g_rep[(size_t)b * HID2x + h]        = Hb[h];
    g_rep[(size_t)b * HID2x + HIDx + h] = s0 / sc0 - s1 / sc1;
}

// ============ K2 (bf16 HMMA hi/lo, fused fp32->bf16 conversion) ============
// CTA = (b, l-half): D[M=128 l][N=128 p], K=768 in 24 chunks of 32.
#define K2_SMEM 65536

__global__ void __launch_bounds__(256) k2_hmma(const float* __restrict__ H) {
    extern __shared__ char sm[];
    uint32_t sb = smem_u32(sm);
    int b = blockIdx.x;
    int l0 = blockIdx.y * 128;
    int tid = threadIdx.x;
    int lane = tid & 31, w = tid >> 5;
    int wm = w >> 2;       // 0..1 : m64 tile
    int wn = w & 3;        // 0..3 : n32 tile

    int srow = tid >> 1;          // 0..127
    int half = tid & 1;           // which 16-elem half of the 32-k chunk
    const float4* gA = reinterpret_cast<const float4*>(H + ((size_t)(b * Lx) + l0 + srow) * HIDx) + half * 4;
    const uint4* gBh = reinterpret_cast<const uint4*>(g_phi + (size_t)srow * HIDx) + half * 2;
    const uint4* gBl = reinterpret_cast<const uint4*>(g_plo + (size_t)srow * HIDx) + half * 2;
    int sw_s = (srow >> 1) & 3;
    uint32_t o0 = (uint32_t)srow * 64 + (uint32_t)(((half * 2)     ^ sw_s) * 16);
    uint32_t o1 = (uint32_t)srow * 64 + (uint32_t)(((half * 2 + 1) ^ sw_s) * 16);
    uint32_t oa[4];
#pragma unroll
    for (int q = 0; q < 4; q++) {
        uint32_t u = (uint32_t)(half * 2 + (q >> 1));
        oa[q] = (uint32_t)srow * 64 + ((u ^ (uint32_t)sw_s) << 4) + (uint32_t)((q & 1) * 8);
    }

    uint32_t rowA[4]; uint32_t swA[4];
#pragma unroll
    for (int i = 0; i < 4; i++) {
        int r = wm * 64 + i * 16 + (lane & 15);
        rowA[i] = (uint32_t)r * 64;
        swA[i] = (uint32_t)((r >> 1) & 3);
    }
    uint32_t ua = (uint32_t)(lane >> 4);        // 0/1
    uint32_t rowB[2]; uint32_t swB[2];
#pragma unroll
    for (int j2 = 0; j2 < 2; j2++) {
        int r = wn * 32 + j2 * 16 + (lane & 7) + ((lane >> 4) << 3);
        rowB[j2] = (uint32_t)r * 64;
        swB[j2] = (uint32_t)((r >> 1) & 3);
    }
    uint32_t ub = (uint32_t)((lane >> 3) & 1);  // 0/1

    float acc[4][4][4];
#pragma unroll
    for (int i = 0; i < 4; i++)
#pragma unroll
        for (int j = 0; j < 4; j++)
#pragma unroll
            for (int r = 0; r < 4; r++) acc[i][j][r] = 0.f;

    float4 pfA[4];
    uint4 pfBh[2], pfBl[2];
    {
#pragma unroll
        for (int q = 0; q < 4; q++) pfA[q] = gA[q];
        pfBh[0] = gBh[0]; pfBh[1] = gBh[1];
        pfBl[0] = gBl[0]; pfBl[1] = gBl[1];
        char* sp = sm;
#pragma unroll
        for (int q = 0; q < 4; q++) {
            uint2 hi, lo;
            cvt4_hilo(pfA[q], hi, lo);
            *reinterpret_cast<uint2*>(sp + 0    + oa[q]) = hi;
            *reinterpret_cast<uint2*>(sp + 8192 + oa[q]) = lo;
        }
        *reinterpret_cast<uint4*>(sp + 16384 + o0) = pfBh[0];
        *reinterpret_cast<uint4*>(sp + 16384 + o1) = pfBh[1];
        *reinterpret_cast<uint4*>(sp + 24576 + o0) = pfBl[0];
        *reinterpret_cast<uint4*>(sp + 24576 + o1) = pfBl[1];
    }
    __syncthreads();

    for (int c = 0; c < 24; c++) {
        int buf = c & 1;
        if (c < 23) {
            int offA = (c + 1) * 8;
            int offB = (c + 1) * 4;
#pragma unroll
            for (int q = 0; q < 4; q++) pfA[q] = gA[offA + q];
            pfBh[0] = gBh[offB]; pfBh[1] = gBh[offB + 1];
            pfBl[0] = gBl[offB]; pfBl[1] = gBl[offB + 1];
        }

        uint32_t bb = sb + (uint32_t)buf * 32768;
#pragma unroll
        for (int sel = 0; sel < 2; sel++) {
            uint32_t u2 = (uint32_t)(sel * 2);
            uint32_t bfh[4][2], bfl[4][2];
#pragma unroll
            for (int j2 = 0; j2 < 2; j2++) {
                uint32_t ah = bb + 16384 + rowB[j2] + (((u2 + ub) ^ swB[j2]) << 4);
                uint32_t r0, r1, r2, r3;
                LDSM4(r0, r1, r2, r3, ah);
                bfh[j2 * 2][0] = r0; bfh[j2 * 2][1] = r1;
                bfh[j2 * 2 + 1][0] = r2; bfh[j2 * 2 + 1][1] = r3;
                uint32_t al = bb + 24576 + rowB[j2] + (((u2 + ub) ^ swB[j2]) << 4);
                LDSM4(r0, r1, r2, r3, al);
                bfl[j2 * 2][0] = r0; bfl[j2 * 2][1] = r1;
                bfl[j2 * 2 + 1][0] = r2; bfl[j2 * 2 + 1][1] = r3;
            }
            uint32_t af[4][4];
#pragma unroll
            for (int i = 0; i < 4; i++) {
                uint32_t a = bb + rowA[i] + (((u2 + ua) ^ swA[i]) << 4);
                LDSM4(af[i][0], af[i][1], af[i][2], af[i][3], a);
            }
#pragma unroll
            for (int i = 0; i < 4; i++)
#pragma unroll
                for (int j = 0; j < 4; j++) {
                    MMA_BF16(acc[i][j], af[i], bfh[j]);
                    MMA_BF16(acc[i][j], af[i], bfl[j]);
                }
#pragma unroll
            for (int i = 0; i < 4; i++) {
                uint32_t a = bb + 8192 + rowA[i] + (((u2 + ua) ^ swA[i]) << 4);
                LDSM4(af[i][0], af[i][1], af[i][2], af[i][3], a);
            }
#pragma unroll
            for (int i = 0; i < 4; i++)
#pragma unroll
                for (int j = 0; j < 4; j++) {
                    MMA_BF16(acc[i][j], af[i], bfh[j]);
                }
        }

        if (c < 23) {
            char* sp = sm + (1 - buf) * 32768;
#pragma unroll
            for (int q = 0; q < 4; q++) {
                uint2 hi, lo;
                cvt4_hilo(pfA[q], hi, lo);
                *reinterpret_cast<uint2*>(sp + 0    + oa[q]) = hi;
                *reinterpret_cast<uint2*>(sp + 8192 + oa[q]) = lo;
            }
            *reinterpret_cast<uint4*>(sp + 16384 + o0) = pfBh[0];
            *reinterpret_cast<uint4*>(sp + 16384 + o1) = pfBh[1];
            *reinterpret_cast<uint4*>(sp + 24576 + o0) = pfBl[0];
            *reinterpret_cast<uint4*>(sp + 24576 + o1) = pfBl[1];
        }
        __syncthreads();
    }

    float* gp = g_Pt + (size_t)b * NPROJx * Lx + l0;
#pragma unroll
    for (int i = 0; i < 4; i++) {
        int lrow = wm * 64 + i * 16 + (lane >> 2);
#pragma unroll
        for (int j = 0; j < 4; j++) {
            int p = wn * 32 + j * 8 + (lane & 3) * 2;
            gp[(size_t)p * Lx + lrow]           = acc[i][j][0];
            gp[(size_t)(p + 1) * Lx + lrow]     = acc[i][j][1];
            gp[(size_t)p * Lx + lrow + 8]       = acc[i][j][2];
            gp[(size_t)(p + 1) * Lx + lrow + 8] = acc[i][j][3];
        }
    }
}

// ===== K3 v2: ONE packed bitonic sort per (b,p); tag in mantissa low bit =====
__device__ __forceinline__ void cex_asc(float& a, float& b) {
    float lo = fminf(a, b);
    float hi = fmaxf(a, b);
    a = lo; b = hi;
}

__device__ __forceinline__ void sort256(float v[8], int lane) {
    const unsigned FULL = 0xffffffffu;
    for (int k = 2; k <= 256; k <<= 1) {
        for (int j = k >> 1; j > 0; j >>= 1) {
            if (j >= 32) {
                int jr = j >> 5;
                int kr = k >> 5;
#pragma unroll
                for (int r = 0; r < 8; r++) {
                    if ((r & jr) == 0) {
                        if ((r & kr) == 0) cex_asc(v[r], v[r | jr]);
                        else               cex_asc(v[r | jr], v[r]);
                    }
                }
            } else {
#pragma unroll
                for (int r = 0; r < 8; r++) {
                    int idx = r * 32 + lane;
                    float other = __shfl_xor_sync(FULL, v[r], j);
                    bool lower = (idx & j) == 0;
                    bool asc   = (idx & k) == 0;
                    bool takeMin = (lower == asc);
                    v[r] = takeMin ? fminf(v[r], other) : fmaxf(v[r], other);
                }
            }
        }
    }
}

__global__ void __launch_bounds__(256) k3_sort(const int* __restrict__ tt,
                                               const int* __restrict__ m) {
    int b = blockIdx.y;
    int tid = threadIdx.x;          // 256 threads = 8 warps
    int warp = tid >> 5, lane = tid & 31;
    __shared__ int tag[Lx];
    __shared__ float sgrp[8][2][256];

    int t = tt[b * Lx + tid];
    int mm = m[b * Lx + tid];
    tag[tid] = (mm == 1) ? t : 2;
    __syncthreads();

    int p = blockIdx.x * 8 + warp;
    const float* col = g_Pt + ((size_t)b * NPROJx + p) * Lx;

    // pack: value with tag in mantissa low bit. tag2 (masked out) -> BIG, group1.
    float v[8];
#pragma unroll
    for (int r = 0; r < 8; r++) {
        int l = r * 32 + lane;
        float val = col[l];
        int tg = tag[l];
        float base = (tg == 2) ? BIGF : val;
        uint32_t u = (__float_as_uint(base) & ~1u) | (uint32_t)(tg != 0);
        v[r] = __uint_as_float(u);
    }
    sort256(v, lane);

    // within-group rank via ballot prefix; scatter to per-group smem arrays
    float* s0 = sgrp[warp][0];
    float* s1 = sgrp[warp][1];
    unsigned below = (1u << lane) - 1u;
    int base1 = 0;
#pragma unroll
    for (int r = 0; r < 8; r++) {
        uint32_t u = __float_as_uint(v[r]);
        int tg = (int)(u & 1u);
        float val = __uint_as_float(u & ~1u);
        unsigned bal = __ballot_sync(0xffffffffu, tg);
        int pre1 = base1 + __popc(bal & below);      // # group1 before idx
        int idx = r * 32 + lane;
        if (tg) s1[pre1] = val;
        else    s0[idx - pre1] = val;
        base1 += __popc(bal);
    }
    __syncwarp();

    int mc = g_mcnt[b];
    float s = 0.f;
#pragma unroll
    for (int r = 0; r < 8; r++) {
        int i = r * 32 + lane;
        if (i < mc) s += fabsf(s0[i] - s1[i]);
    }
#pragma unroll
    for (int o = 16; o > 0; o >>= 1) s += __shfl_down_sync(0xffffffffu, s, o);

    if (lane == 0) {
        float mean = s / (float)max(mc, 1);
        atomicMax(reinterpret_cast<int*>(&g_feat[b * FDIMx + 320]), __float_as_int(mean));
    }
}

// ===== K4a: feature GEMM (split-K z=32): partial[z][b][f] = sum_k rep*W =====
__global__ void __launch_bounds__(256) k4a_featgemm(const float* __restrict__ Wc,
                                                    const float* __restrict__ Ws) {
    __shared__ float repS[16][32];
    __shared__ float wS[16][64];

    int ftile = blockIdx.x * 64;   // 0..4
    int btile = blockIdx.y * 32;   // 0..3
    int kc    = blockIdx.z * 48;   // 0..31
    int tid = threadIdx.x;
    int tx = tid & 15;
    int ty = tid >> 4;

    float acc[2][4];
#pragma unroll
    for (int i = 0; i < 2; i++)
#pragma unroll
        for (int j = 0; j < 4; j++) acc[i][j] = 0.f;

    for (int k0 = 0; k0 < 48; k0 += 16) {
#pragma unroll
        for (int q = 0; q < 2; q++) {
            int e = tid + q * 256;
            int kk = e & 15, bb = e >> 4;
            repS[kk][bb] = g_rep[(size_t)(btile + bb) * HID2x + kc + k0 + kk];
        }
#pragma unroll
        for (int q = 0; q < 4; q++) {
            int e = tid + q * 256;
            int kk = e & 15, ff = e >> 4;
            int f = ftile + ff;
            const float* Wr = (f < CDIMx) ? (Wc + (size_t)f * HID2x)
                                          : (Ws + (size_t)(f - CDIMx) * HID2x);
            wS[kk][ff] = Wr[kc + k0 + kk];
        }
        __syncthreads();

#pragma unroll
        for (int kk = 0; kk < 16; kk++) {
            float4 wv = *reinterpret_cast<const float4*>(&wS[kk][tx * 4]);
            float r0 = repS[kk][ty * 2];
            float r1 = repS[kk][ty * 2 + 1];
            acc[0][0] += r0 * wv.x; acc[0][1] += r0 * wv.y;
            acc[0][2] += r0 * wv.z; acc[0][3] += r0 * wv.w;
            acc[1][0] += r1 * wv.x; acc[1][1] += r1 * wv.y;
            acc[1][2] += r1 * wv.z; acc[1][3] += r1 * wv.w;
        }
        __syncthreads();
    }

#pragma unroll
    for (int i = 0; i < 2; i++) {
        int bb = btile + ty * 2 + i;
        float4 o = make_float4(acc[i][0], acc[i][1], acc[i][2], acc[i][3]);
        *reinterpret_cast<float4*>(&g_partial[((size_t)blockIdx.z * Bx + bb) * 320 + ftile + tx * 4]) = o;
    }
}

// ===== K5: combine split-K + gate, LayerNorm(321), classifier =========
__device__ __forceinline__ float blockReduceSum(float val, float* sbuf) {
    int tid = threadIdx.x;
#pragma unroll
    for (int o = 16; o > 0; o >>= 1) val += __shfl_down_sync(0xffffffffu, val, o);
    if ((tid & 31) == 0) sbuf[tid >> 5] = val;
    __syncthreads();
    if (tid < 32) {
        int nw = (blockDim.x + 31) >> 5;
        float r = (tid < nw) ? sbuf[tid] : 0.f;
#pragma unroll
        for (int o = 16; o > 0; o >>= 1) r += __shfl_down_sync(0xffffffffu, r, o);
        if (tid == 0) sbuf[32] = r;
    }
    __syncthreads();
    float out = sbuf[32];
    __syncthreads();
    return out;
}

__global__ void k5_ln_cls(const float* __restrict__ bc,
                          const float* __restrict__ bs,
                          const float* __restrict__ gate,
                          const float* __restrict__ ln_g,
                          const float* __restrict__ ln_b,
                          const float* __restrict__ Wcls,
                          const float* __restrict__ bcls,
                          float* __restrict__ out) {
    __shared__ float sbuf[33];
    int b = blockIdx.x;
    int f = threadIdx.x; // 384 threads
    bool act = (f < FDIMx);

    float x = 0.f;
    if (f < 320) {
        float s = 0.f;
#pragma unroll
        for (int z = 0; z < 32; z++) s += g_partial[((size_t)z * Bx + b) * 320 + f];
        float g = 1.f / (1.f + expf(-gate[0]));
        if (f < CDIMx) x = (s + bc[f]) * (1.f - g);
        else           x = (s + bs[f - CDIMx]) * g;
    } else if (f == 320) {
        x = g_feat[b * FDIMx + 320];
    }

    float S  = blockReduceSum(x, sbuf);
    float SS = blockReduceSum(x * x, sbuf);
    float mean = S / (float)FDIMx;
    float var  = SS / (float)FDIMx - mean * mean;
    float inv  = rsqrtf(var + 1e-5f);

    float nrm = act ? ((x - mean) * inv * ln_g[f] + ln_b[f]) : 0.f;
    float w0 = act ? Wcls[f] : 0.f;
    float w1 = act ? Wcls[FDIMx + f] : 0.f;

    float s0 = blockReduceSum(nrm * w0, sbuf);
    float s1 = blockReduceSum(nrm * w1, sbuf);
    if (f == 0) {
        out[b * 2 + 0] = s0 + bcls[0];
        out[b * 2 + 1] = s1 + bcls[1];
    }
}

// =================================== launch ======================================
extern "C" void kernel_launch(void* const* d_in, const int* in_sizes, int n_in,
                              void* d_out, int out_size) {
    const float* H    = (const float*)d_in[0];
    const int*   tt   = (const int*)d_in[1];
    const int*   m    = (const int*)d_in[2];
    const float* Wc   = (const float*)d_in[3];
    const float* bc   = (const float*)d_in[4];
    const float* Ws   = (const float*)d_in[5];
    const float* bs   = (const float*)d_in[6];
    const float* gate = (const float*)d_in[7];
    const float* ln_g = (const float*)d_in[8];
    const float* ln_b = (const float*)d_in[9];
    const float* Wcls = (const float*)d_in[10];
    const float* bcls = (const float*)d_in[11];
    const float* proj = (const float*)d_in[12];
    float* out = (float*)d_out;

    cudaFuncSetAttribute(k2_hmma, cudaFuncAttributeMaxDynamicSharedMemorySize, K2_SMEM);

    k0_cvt_proj<<<96, 256>>>(proj, (NPROJx * HIDx) / 4);
    k1_stats<<<dim3(Bx, 3), 256>>>(H, tt, m);
    k2_hmma<<<dim3(Bx, 2), 256, K2_SMEM>>>(H);
    k3_sort<<<dim3(16, Bx), 256>>>(tt, m);
    k4a_featgemm<<<dim3(5, 4, 32), 256>>>(Wc, Ws);
    k5_ln_cls<<<Bx, 384>>>(bc, bs, gate, ln_g, ln_b, Wcls, bcls, out);
}